// round 11
// baseline (speedup 1.0000x reference)
#include <cuda_runtime.h>
#include <cstdint>

// CRF forward scan. 128-thread blocks = TWO independent 64-thread engines:
// warps 0-1 (SMSP 0,1) -> batch 2b, warps 2-3 (SMSP 2,3) -> batch 2b+1.
// Engines sync only via per-pair named barriers (no cross-pair coupling).
// Per engine (lean R10 body): thread tid64=32*w2+lane owns state tid64; each
// thread computes partial sums over its warp's v-half for columns tid64
// (kept) and tid64^32 (published, 1 float). Shift m = stale-by-1 alpha[1]
// (block-uniform; LSE shift-invariant). alpha base-2 scaled, ex2/lg2 approx.
// feats/masks staged via cp.async 3-buffer pipeline.

#define TT 64
#define CHUNK 16
#define L2E 1.4426950408889634f
#define LN2 0.6931471805599453f
typedef unsigned long long u64;

__device__ float g_Wt[TT * TT];  // g_Wt[j*64+i] = exp(trans[i][j]-c_j)
__device__ float g_c2[TT];       // c_j * log2(e)

__device__ __forceinline__ void unpack2(u64 v, float& lo, float& hi) {
    asm("mov.b64 {%0, %1}, %2;" : "=f"(lo), "=f"(hi) : "l"(v));
}
__device__ __forceinline__ u64 ffma2(u64 a, u64 b, u64 c) {
    u64 d; asm("fma.rn.f32x2 %0, %1, %2, %3;" : "=l"(d) : "l"(a), "l"(b), "l"(c)); return d;
}
__device__ __forceinline__ u64 fadd2(u64 a, u64 b) {
    u64 d; asm("add.rn.f32x2 %0, %1, %2;" : "=l"(d) : "l"(a), "l"(b)); return d;
}
__device__ __forceinline__ float ex2f(float x) {
    float y; asm("ex2.approx.f32 %0, %1;" : "=f"(y) : "f"(x)); return y;
}
__device__ __forceinline__ float lg2f(float x) {
    float y; asm("lg2.approx.f32 %0, %1;" : "=f"(y) : "f"(x)); return y;
}
__device__ __forceinline__ uint32_t smem_u32(const void* p) {
    uint32_t a;
    asm("{ .reg .u64 t; cvta.to.shared.u64 t, %1; cvt.u32.u64 %0, t; }" : "=r"(a) : "l"(p));
    return a;
}
__device__ __forceinline__ void barpair(int barid) {
    asm volatile("bar.sync %0, 64;" :: "r"(barid) : "memory");
}

// ---------------------------------------------------------------------------
__global__ void crf_prep_kernel(const float* __restrict__ trans) {
    int j = threadIdx.x;
    float c = -3.402823466e+38f;
    #pragma unroll
    for (int i = 0; i < TT; i++) c = fmaxf(c, trans[i * TT + j]);
    g_c2[j] = c * L2E;
    #pragma unroll
    for (int i = 0; i < TT; i++) g_Wt[j * TT + i] = __expf(trans[i * TT + j] - c);
}

// ---------------------------------------------------------------------------
__global__ void __launch_bounds__(128) crf_scan_kernel(
    const float* __restrict__ feats,   // [B, S, 64]
    const float* __restrict__ masks,   // [B, S]
    float* __restrict__ out,           // [B, 64]
    int Sdim, int Bn)
{
    const int warp  = threadIdx.x >> 5;   // 0..3 -> SMSP 0..3
    const int lane  = threadIdx.x & 31;
    const int pair  = warp >> 1;           // engine id (0/1)
    const int w2    = warp & 1;            // warp within engine
    const int tid64 = w2 * 32 + lane;      // owned state
    int b = blockIdx.x * 2 + pair;
    if (b >= Bn) b = Bn - 1;               // duplicate work, identical writes
    const int barid = pair + 1;

    __shared__ alignas(16) float s_feat[2][3][CHUNK][TT];  // 24 KB
    __shared__ float s_mask[2][3][CHUNK];
    __shared__ alignas(16) float s_v[2][2][TT];            // [pair][buf][state]
    __shared__ float s_part[2][2][TT];
    __shared__ float s_mring[2][2];

    // Per-pair base pointers hoisted to registers (zero per-step ALU).
    float (*featp)[CHUNK][TT] = s_feat[pair];
    float (*maskp)[CHUNK]     = s_mask[pair];
    float (*vp2)[TT]          = s_v[pair];
    float (*partp)[TT]        = s_part[pair];
    float* mring              = s_mring[pair];

    // W columns tid64 (own) and tid64^32, rows [32*w2, 32*w2+32), pre-packed.
    u64 wA[16], wB[16];
    {
        const ulonglong2* pa =
            reinterpret_cast<const ulonglong2*>(&g_Wt[tid64 * TT + 32 * w2]);
        const ulonglong2* pb =
            reinterpret_cast<const ulonglong2*>(&g_Wt[(tid64 ^ 32) * TT + 32 * w2]);
        #pragma unroll
        for (int q = 0; q < 8; q++) {
            ulonglong2 ua = pa[q];
            wA[2 * q]     = ua.x;
            wA[2 * q + 1] = ua.y;
            ulonglong2 ub = pb[q];
            wB[2 * q]     = ub.x;
            wB[2 * q + 1] = ub.y;
        }
    }
    const float cj2 = g_c2[tid64];

    const float* fbp = feats + (size_t)b * Sdim * TT;
    const float* mbp = masks + (size_t)b * Sdim;
    const uint32_t feat_s0 = smem_u32(&featp[0][0][0]);
    const uint32_t mask_s0 = smem_u32(&maskp[0][0]);

    const int NC = (Sdim + CHUNK - 1) / CHUNK;

    // Stage chunk c into this pair's buffer c%3 — fully async, 64 threads.
    auto stage = [&](int c) {
        const int base = c * CHUNK;
        const int bufo = (c % 3) * CHUNK * TT;
        #pragma unroll
        for (int q = 0; q < 4; q++) {
            int g   = q * 64 + tid64;      // 16B granule 0..255
            int row = g >> 4;
            int col = (g & 15) << 2;
            int gr  = base + row; if (gr >= Sdim) gr = Sdim - 1;
            const float* src = fbp + (size_t)gr * TT + col;
            uint32_t dst = feat_s0 + (uint32_t)(bufo + row * TT + col) * 4u;
            asm volatile("cp.async.cg.shared.global [%0], [%1], 16;" :: "r"(dst), "l"(src));
        }
        if (tid64 < CHUNK) {
            int gr = base + tid64; if (gr >= Sdim) gr = Sdim - 1;
            const float* src = mbp + gr;
            uint32_t dst = mask_s0 + (uint32_t)((c % 3) * CHUNK + tid64) * 4u;
            asm volatile("cp.async.ca.shared.global [%0], [%1], 4;" :: "r"(dst), "l"(src));
        }
    };

    stage(0);
    asm volatile("cp.async.commit_group;");
    if (NC > 1) stage(1);
    asm volatile("cp.async.commit_group;");
    asm volatile("cp.async.wait_group 1;");
    barpair(barid);

    float alpha = featp[0][0][tid64] * L2E;   // base-2 scaled alpha0

    // Seed shift ring: slot 1 read at t=1 (slot = r&1).
    if (tid64 == 1) mring[1] = alpha;
    barpair(barid);
    float m = mring[1];

    for (int c = 0; c < NC; c++) {
        if (c > 0) asm volatile("cp.async.wait_group 1;");
        if (c + 2 < NC) stage(c + 2);
        asm volatile("cp.async.commit_group;");
        barpair(barid);

        #pragma unroll
        for (int r = 0; r < CHUNK; r++) {
            const int t = c * CHUNK + r;
            if (t >= 1 && t < Sdim) {
                // Chain head: exp2 with stale shift, publish own v.
                const float v = ex2f(alpha - m);
                vp2[r & 1][tid64] = v;

                // Publish alpha[1] for step t+1's shift.
                if (tid64 == 1) mring[(r & 1) ^ 1] = alpha;

                // Off-chain: staged feat/mask, blend precompute.
                const float ft  = featp[c % 3][r][tid64];
                const float mk  = maskp[c % 3][r];
                const float pre = fmaf(ft, L2E, cj2 + m);
                const float t0  = fmaf(mk, pre - alpha, alpha);

                __syncwarp();

                // Own-half matvec for columns tid64 and tid64^32.
                const ulonglong2* vp =
                    reinterpret_cast<const ulonglong2*>(&vp2[r & 1][32 * w2]);
                u64 accA[4] = {0ull, 0ull, 0ull, 0ull};
                u64 accB[4] = {0ull, 0ull, 0ull, 0ull};
                #pragma unroll
                for (int q = 0; q < 8; q++) {
                    ulonglong2 u = vp[q];
                    accA[(2 * q) & 3]     = ffma2(u.x, wA[2 * q],     accA[(2 * q) & 3]);
                    accA[(2 * q + 1) & 3] = ffma2(u.y, wA[2 * q + 1], accA[(2 * q + 1) & 3]);
                    accB[(2 * q) & 3]     = ffma2(u.x, wB[2 * q],     accB[(2 * q) & 3]);
                    accB[(2 * q + 1) & 3] = ffma2(u.y, wB[2 * q + 1], accB[(2 * q + 1) & 3]);
                }
                u64 sA = fadd2(fadd2(accA[0], accA[1]), fadd2(accA[2], accA[3]));
                u64 sB = fadd2(fadd2(accB[0], accB[1]), fadd2(accB[2], accB[3]));
                float al, ah, bl, bh;
                unpack2(sA, al, ah);
                unpack2(sB, bl, bh);
                const float PA = al + ah;   // partial for OWN column tid64
                const float PB = bl + bh;   // partial for column tid64^32

                partp[r & 1][tid64 ^ 32] = PB;

                barpair(barid);

                // Tail: combine halves, log2, blend; fetch next shift.
                const float P = PA + partp[r & 1][tid64];
                alpha = fmaf(lg2f(P), mk, t0);
                m = mring[(r & 1) ^ 1];
            }
        }
    }

    out[(size_t)b * TT + tid64] = alpha * LN2;
}

// ---------------------------------------------------------------------------
extern "C" void kernel_launch(void* const* d_in, const int* in_sizes, int n_in,
                              void* d_out, int out_size) {
    const float* feats = (const float*)d_in[0];
    const float* masks = (const float*)d_in[1];
    const float* trans = (const float*)d_in[2];
    float* out = (float*)d_out;

    const int Bn   = out_size / TT;
    const int Sdim = in_sizes[0] / (Bn * TT);

    crf_prep_kernel<<<1, TT>>>(trans);
    crf_scan_kernel<<<(Bn + 1) / 2, 128>>>(feats, masks, out, Sdim, Bn);
}